// round 5
// baseline (speedup 1.0000x reference)
#include <cuda_runtime.h>
#include <cuda_bf16.h>
#include <cstdint>

// out [4,2048,1024] f32 = X@W1^T + b1 + pooled@W2^T + b2
// Main GEMM: warp-level mma.sync bf16 (sm_100 base target; tcgen05 unavailable)
// with split-bf16 hi/lo 3-MMA fp32 emulation. 512 threads / 16 warps per CTA
// for 4 warps/SMSP issue density.

static constexpr int BATCH = 4;
static constexpr int LSEQ  = 2048;
static constexpr int DDIM  = 1024;
static constexpr int MROWS = BATCH * LSEQ;   // 8192
static constexpr int NCOLS = DDIM;
static constexpr int KDIM  = DDIM;

// ---------------- device scratch ----------------
__device__ unsigned long long g_codes[MROWS];
__device__ float g_pooled[(size_t)MROWS * DDIM];
__device__ int g_wl[MROWS];
__device__ int g_wl_count;
__device__ int g_ids_is64;
__device__ __align__(256) __nv_bfloat16 g_Ahi[(size_t)MROWS * KDIM];
__device__ __align__(256) __nv_bfloat16 g_Alo[(size_t)MROWS * KDIM];
__device__ __align__(256) __nv_bfloat16 g_Bhi[(size_t)NCOLS * KDIM];
__device__ __align__(256) __nv_bfloat16 g_Blo[(size_t)NCOLS * KDIM];

// ====================== PTX helpers (sm_80+ portable) ======================
__device__ __forceinline__ uint32_t smem_u32(const void* p) {
    uint32_t a;
    asm("{ .reg .u64 t; cvta.to.shared.u64 t, %1; cvt.u32.u64 %0, t; }" : "=r"(a) : "l"(p));
    return a;
}
__device__ __forceinline__ void cp16(uint32_t dst, const void* src) {
    asm volatile("cp.async.cg.shared.global [%0], [%1], 16;" :: "r"(dst), "l"(src));
}
#define CP_COMMIT() asm volatile("cp.async.commit_group;" ::: "memory")
#define CP_WAIT(n)  asm volatile("cp.async.wait_group %0;" :: "n"(n) : "memory")

__device__ __forceinline__ void ldsm_x4(uint32_t* r, uint32_t addr) {
    asm volatile("ldmatrix.sync.aligned.m8n8.x4.shared.b16 {%0,%1,%2,%3}, [%4];"
        : "=r"(r[0]), "=r"(r[1]), "=r"(r[2]), "=r"(r[3]) : "r"(addr));
}
__device__ __forceinline__ void ldsm_x2(uint32_t* r, uint32_t addr) {
    asm volatile("ldmatrix.sync.aligned.m8n8.x2.shared.b16 {%0,%1}, [%2];"
        : "=r"(r[0]), "=r"(r[1]) : "r"(addr));
}
__device__ __forceinline__ void mma_bf16(float* c, const uint32_t* a, const uint32_t* b) {
    asm volatile("mma.sync.aligned.m16n8k16.row.col.f32.bf16.bf16.f32 "
        "{%0,%1,%2,%3}, {%4,%5,%6,%7}, {%8,%9}, {%0,%1,%2,%3};"
        : "+f"(c[0]), "+f"(c[1]), "+f"(c[2]), "+f"(c[3])
        : "r"(a[0]), "r"(a[1]), "r"(a[2]), "r"(a[3]), "r"(b[0]), "r"(b[1]));
}

// ---------------- kernel 0: detect ids dtype + reset worklist ----------------
__global__ void detect_kernel(const unsigned int* __restrict__ w)
{
    __shared__ int s_any;
    if (threadIdx.x == 0) s_any = 0;
    __syncthreads();
    for (int i = 2 * threadIdx.x + 1; i < MROWS; i += 2 * blockDim.x)
        if (w[i] != 0u) s_any = 1;
    __syncthreads();
    if (threadIdx.x == 0) {
        g_ids_is64 = (s_any == 0) ? 1 : 0;
        g_wl_count = 0;
    }
}

// ---------------- kernel 1: pack n-gram codes ----------------
__global__ void prep_codes_kernel(const void* __restrict__ ids_raw,
                                  const int* __restrict__ n_ptr)
{
    int idx = blockIdx.x * blockDim.x + threadIdx.x;
    if (idx >= MROWS) return;
    int n = *n_ptr;
    int is64 = g_ids_is64;
    const int*       i32 = (const int*)ids_raw;
    const long long* i64 = (const long long*)ids_raw;
    int b = idx / LSEQ;
    int q = idx % LSEQ;
    unsigned long long code = 0ull;
    if (q >= n - 1) {
        for (int i = 0; i < n; i++) {
            int pos = b * LSEQ + (q - n + 1 + i);
            long long v = is64 ? i64[pos] : (long long)i32[pos];
            code = (code << 16) | (unsigned long long)(v & 0xFFFF);
        }
    }
    g_codes[idx] = code;
}

// ---------------- kernel 2: matches -> pooled rows + worklist ----------------
__global__ __launch_bounds__(256) void pool_kernel(const float* __restrict__ hidden)
{
    __shared__ int s_match[LSEQ];
    __shared__ int s_cnt;
    int blk = blockIdx.x;
    int tid = threadIdx.x;
    int b = blk / LSEQ;
    int q = blk % LSEQ;
    if (tid == 0) s_cnt = 0;
    __syncthreads();
    unsigned long long myc = g_codes[blk];
    for (int k = tid; k < q; k += 256) {
        if (g_codes[b * LSEQ + k] == myc) {
            int pos = atomicAdd(&s_cnt, 1);
            s_match[pos] = k;
        }
    }
    __syncthreads();
    int cnt = s_cnt;
    if (cnt == 0) return;
    if (tid == 0) {
        int wi = atomicAdd(&g_wl_count, 1);
        g_wl[wi] = blk;
    }
    int c = tid * 4;
    float4 acc = make_float4(0.f, 0.f, 0.f, 0.f);
    for (int m = 0; m < cnt; m++) {
        const float4 h = *(const float4*)&hidden[((size_t)b * LSEQ + s_match[m]) * DDIM + c];
        acc.x += h.x; acc.y += h.y; acc.z += h.z; acc.w += h.w;
    }
    float inv = 1.0f / (float)cnt;
    acc.x *= inv; acc.y *= inv; acc.z *= inv; acc.w *= inv;
    *(float4*)&g_pooled[(size_t)blk * DDIM + c] = acc;
}

// ---------------- kernel: fp32 -> bf16 hi/lo split (X and W1 in one launch) ----------------
__global__ void convert_kernel(const float* __restrict__ srcA,
                               __nv_bfloat16* __restrict__ dAhi,
                               __nv_bfloat16* __restrict__ dAlo,
                               const float* __restrict__ srcB,
                               __nv_bfloat16* __restrict__ dBhi,
                               __nv_bfloat16* __restrict__ dBlo)
{
    const int A4 = MROWS * KDIM / 4;       // 2M float4
    const int B4 = NCOLS * KDIM / 4;       // 256K float4
    int gid = blockIdx.x * blockDim.x + threadIdx.x;
    int stride = gridDim.x * blockDim.x;
    for (int i = gid; i < A4 + B4; i += stride) {
        const float* src; __nv_bfloat16 *dhi, *dlo; int j;
        if (i < A4) { src = srcA; dhi = dAhi; dlo = dAlo; j = i; }
        else        { src = srcB; dhi = dBhi; dlo = dBlo; j = i - A4; }
        float4 v = ((const float4*)src)[j];
        __nv_bfloat16 h0 = __float2bfloat16_rn(v.x);
        __nv_bfloat16 h1 = __float2bfloat16_rn(v.y);
        __nv_bfloat16 h2 = __float2bfloat16_rn(v.z);
        __nv_bfloat16 h3 = __float2bfloat16_rn(v.w);
        __nv_bfloat16 l0 = __float2bfloat16_rn(v.x - __bfloat162float(h0));
        __nv_bfloat16 l1 = __float2bfloat16_rn(v.y - __bfloat162float(h1));
        __nv_bfloat16 l2 = __float2bfloat16_rn(v.z - __bfloat162float(h2));
        __nv_bfloat16 l3 = __float2bfloat16_rn(v.w - __bfloat162float(h3));
        ((__nv_bfloat162*)dhi)[2 * j + 0] = __nv_bfloat162(h0, h1);
        ((__nv_bfloat162*)dhi)[2 * j + 1] = __nv_bfloat162(h2, h3);
        ((__nv_bfloat162*)dlo)[2 * j + 0] = __nv_bfloat162(l0, l1);
        ((__nv_bfloat162*)dlo)[2 * j + 1] = __nv_bfloat162(l2, l3);
    }
}

// ---------------- kernel 3: HMMA split-bf16 GEMM  C = X@W1^T + b1 + b2 ----------------
// CTA tile 128x256, BK=64 (128B swizzled rows). 512 threads / 16 warps (4x4),
// warp tile 32x64 (acc = 64 regs). 2-stage cp.async double buffer.
// Per k16: ld(ahi,bhi)->hihi; ld(alo)->lohi; ld(blo)->hilo (caps live regs).
static constexpr int TBM = 128, TBN = 256, TBK = 64;
static constexpr int N_CHUNKS = KDIM / TBK;                      // 16
static constexpr int ST_AHI = 0, ST_ALO = 16384, ST_BHI = 32768, ST_BLO = 65536;
static constexpr int STAGE_BYTES = 98304;                        // 96KB
static constexpr int SMEM_DYN = 1024 + 2 * STAGE_BYTES;

__global__ __launch_bounds__(512, 1)
void gemm_mma_kernel(const float* __restrict__ b1,
                     const float* __restrict__ b2,
                     float* __restrict__ C)
{
    extern __shared__ char smem[];
    uint32_t sbase = (smem_u32(smem) + 1023u) & ~1023u;

    int tid  = threadIdx.x;
    int wid  = tid >> 5;
    int lane = tid & 31;
    int row0 = blockIdx.y * TBM;
    int col0 = blockIdx.x * TBN;

    int wm = wid >> 2;            // 0..3  -> M offset 32 each
    int wn = wid & 3;             // 0..3  -> N offset 64 each
    int mbase = wm * 32;
    int nbase = wn * 64;

    // ldmatrix address components
    int arow_l = (lane & 15);
    int aklane = (lane >> 4) * 16;
    uint32_t aoffs[2], axors[2];
#pragma unroll
    for (int i = 0; i < 2; i++) {
        int r = mbase + 16 * i + arow_l;
        aoffs[i] = (uint32_t)(r * 128);
        axors[i] = (uint32_t)((r & 7) << 4);
    }
    int brow_l = (lane & 7);
    int bklane = ((lane >> 3) & 1) * 16;
    uint32_t bxor = (uint32_t)(brow_l << 4);
    uint32_t boffs[8];
#pragma unroll
    for (int j = 0; j < 8; j++)
        boffs[j] = (uint32_t)((nbase + 8 * j + brow_l) * 128);

    float acc[2][8][4];
#pragma unroll
    for (int i = 0; i < 2; i++)
#pragma unroll
        for (int j = 0; j < 8; j++)
#pragma unroll
            for (int t = 0; t < 4; t++) acc[i][j][t] = 0.f;

    auto load_chunk = [&](int c, uint32_t sb) {
        int k0 = c * TBK;
#pragma unroll
        for (int i = tid; i < 1024; i += 512) {        // A: 128 rows x 8 chunks
            int r = i >> 3, c16 = i & 7;
            uint32_t off = (uint32_t)(r * 128 + c16 * 16) ^ (uint32_t)((r & 7) << 4);
            size_t src = (size_t)(row0 + r) * KDIM + k0 + c16 * 8;
            cp16(sb + ST_AHI + off, &g_Ahi[src]);
            cp16(sb + ST_ALO + off, &g_Alo[src]);
        }
#pragma unroll
        for (int i = tid; i < 2048; i += 512) {        // B: 256 rows x 8 chunks
            int r = i >> 3, c16 = i & 7;
            uint32_t off = (uint32_t)(r * 128 + c16 * 16) ^ (uint32_t)((r & 7) << 4);
            size_t src = (size_t)(col0 + r) * KDIM + k0 + c16 * 8;
            cp16(sb + ST_BHI + off, &g_Bhi[src]);
            cp16(sb + ST_BLO + off, &g_Blo[src]);
        }
        CP_COMMIT();
    };

    load_chunk(0, sbase);

    for (int c = 0; c < N_CHUNKS; c++) {
        uint32_t sb = sbase + (uint32_t)(c & 1) * STAGE_BYTES;
        if (c + 1 < N_CHUNKS) {
            load_chunk(c + 1, sbase + (uint32_t)((c + 1) & 1) * STAGE_BYTES);
            CP_WAIT(1);
        } else {
            CP_WAIT(0);
        }
        __syncthreads();

#pragma unroll
        for (int ks = 0; ks < 4; ks++) {
            uint32_t kb = (uint32_t)(ks * 32);
            uint32_t akcol = kb + (uint32_t)aklane;
            uint32_t bkcol = kb + (uint32_t)bklane;

            uint32_t ahi[2][4], bhi[8][2];
#pragma unroll
            for (int i = 0; i < 2; i++)
                ldsm_x4(ahi[i], sb + ST_AHI + aoffs[i] + (akcol ^ axors[i]));
#pragma unroll
            for (int j = 0; j < 8; j++)
                ldsm_x2(bhi[j], sb + ST_BHI + boffs[j] + (bkcol ^ bxor));
#pragma unroll
            for (int i = 0; i < 2; i++)
#pragma unroll
                for (int j = 0; j < 8; j++)
                    mma_bf16(acc[i][j], ahi[i], bhi[j]);

            {   // lo(A) x hi(B)
                uint32_t alo[2][4];
#pragma unroll
                for (int i = 0; i < 2; i++)
                    ldsm_x4(alo[i], sb + ST_ALO + aoffs[i] + (akcol ^ axors[i]));
#pragma unroll
                for (int i = 0; i < 2; i++)
#pragma unroll
                    for (int j = 0; j < 8; j++)
                        mma_bf16(acc[i][j], alo[i], bhi[j]);
            }
            {   // hi(A) x lo(B)
                uint32_t blo[8][2];
#pragma unroll
                for (int j = 0; j < 8; j++)
                    ldsm_x2(blo[j], sb + ST_BLO + boffs[j] + (bkcol ^ bxor));
#pragma unroll
                for (int i = 0; i < 2; i++)
#pragma unroll
                    for (int j = 0; j < 8; j++)
                        mma_bf16(acc[i][j], ahi[i], blo[j]);
            }
        }
        __syncthreads();
    }

    // ---- epilogue: fused bias, register -> gmem ----
    int quad = lane >> 2;
    int tq   = lane & 3;
#pragma unroll
    for (int j = 0; j < 8; j++) {
        int col = col0 + nbase + 8 * j + tq * 2;
        float2 s1 = *(const float2*)&b1[col];
        float2 s2 = *(const float2*)&b2[col];
        float bx = s1.x + s2.x, by = s1.y + s2.y;
#pragma unroll
        for (int i = 0; i < 2; i++) {
            int r0 = row0 + mbase + 16 * i + quad;
            *(float2*)&C[(size_t)r0 * NCOLS + col] =
                make_float2(acc[i][j][0] + bx, acc[i][j][1] + by);
            *(float2*)&C[(size_t)(r0 + 8) * NCOLS + col] =
                make_float2(acc[i][j][2] + bx, acc[i][j][3] + by);
        }
    }
}

// ---------------- kernel 4: sparse fixup  out[row] += pooled[row] @ W2^T ----------------
__global__ __launch_bounds__(256) void fixup_kernel(const float* __restrict__ W2,
                                                    float* __restrict__ C)
{
    int slot = blockIdx.x;
    if (slot >= g_wl_count) return;
    int row = g_wl[slot];

    __shared__ float s_x[DDIM];
    int tid = threadIdx.x;
    for (int d = tid; d < DDIM; d += 256) s_x[d] = g_pooled[(size_t)row * DDIM + d];
    __syncthreads();

    int warp = tid / 32;
    int lane = tid % 32;
    for (int j = warp * 128; j < warp * 128 + 128; j++) {
        const float* wrow = &W2[(size_t)j * KDIM];
        float sum = 0.f;
        for (int d = lane; d < KDIM; d += 32) sum += s_x[d] * wrow[d];
#pragma unroll
        for (int off = 16; off > 0; off >>= 1)
            sum += __shfl_down_sync(0xFFFFFFFFu, sum, off);
        if (lane == 0) C[(size_t)row * NCOLS + j] += sum;
    }
}

// ---------------- launch ----------------
extern "C" void kernel_launch(void* const* d_in, const int* in_sizes, int n_in,
                              void* d_out, int out_size)
{
    const float* hidden = (const float*)d_in[0];
    const void*  ids    = d_in[1];
    const float* W1     = (const float*)d_in[2];
    const float* b1     = (const float*)d_in[3];
    const float* W2     = (const float*)d_in[4];
    const float* b2     = (const float*)d_in[5];
    const int*   n_ptr  = (const int*)d_in[6];
    float*       out    = (float*)d_out;

    static bool attr_done = false;
    if (!attr_done) {
        cudaFuncSetAttribute(gemm_mma_kernel,
                             cudaFuncAttributeMaxDynamicSharedMemorySize, SMEM_DYN);
        attr_done = true;
    }

    void *pAhi, *pAlo, *pBhi, *pBlo;
    cudaGetSymbolAddress(&pAhi, g_Ahi);
    cudaGetSymbolAddress(&pAlo, g_Alo);
    cudaGetSymbolAddress(&pBhi, g_Bhi);
    cudaGetSymbolAddress(&pBlo, g_Blo);

    detect_kernel<<<1, 1024>>>((const unsigned int*)ids);
    prep_codes_kernel<<<(MROWS + 255) / 256, 256>>>(ids, n_ptr);
    convert_kernel<<<2304, 256>>>(hidden, (__nv_bfloat16*)pAhi, (__nv_bfloat16*)pAlo,
                                  W1, (__nv_bfloat16*)pBhi, (__nv_bfloat16*)pBlo);
    pool_kernel<<<MROWS, 256>>>(hidden);
    dim3 ggrid(NCOLS / TBN, MROWS / TBM);   // (4, 64)
    gemm_mma_kernel<<<ggrid, 512, SMEM_DYN>>>(b1, b2, out);
    fixup_kernel<<<MROWS, 256>>>(W2, out);
}

// round 6
// speedup vs baseline: 1.1055x; 1.1055x over previous
#include <cuda_runtime.h>
#include <cuda_bf16.h>
#include <cstdint>

// out [4,2048,1024] f32 = X@W1^T + b1 + pooled@W2^T + b2
// Main GEMM: warp-level mma.sync bf16 (sm_100 base target; tcgen05 unavailable)
// with split-bf16 hi/lo 3-MMA fp32 emulation. 256 threads / 8 warps (2x4),
// warp tile 64x64, j-blocked inner loop to cap live registers (no spills).

static constexpr int BATCH = 4;
static constexpr int LSEQ  = 2048;
static constexpr int DDIM  = 1024;
static constexpr int MROWS = BATCH * LSEQ;   // 8192
static constexpr int NCOLS = DDIM;
static constexpr int KDIM  = DDIM;

// ---------------- device scratch ----------------
__device__ unsigned long long g_codes[MROWS];
__device__ float g_pooled[(size_t)MROWS * DDIM];
__device__ int g_wl[MROWS];
__device__ int g_wl_count;
__device__ int g_ids_is64;
__device__ __align__(256) __nv_bfloat16 g_Ahi[(size_t)MROWS * KDIM];
__device__ __align__(256) __nv_bfloat16 g_Alo[(size_t)MROWS * KDIM];
__device__ __align__(256) __nv_bfloat16 g_Bhi[(size_t)NCOLS * KDIM];
__device__ __align__(256) __nv_bfloat16 g_Blo[(size_t)NCOLS * KDIM];

// ====================== PTX helpers (sm_80+ portable) ======================
__device__ __forceinline__ uint32_t smem_u32(const void* p) {
    uint32_t a;
    asm("{ .reg .u64 t; cvta.to.shared.u64 t, %1; cvt.u32.u64 %0, t; }" : "=r"(a) : "l"(p));
    return a;
}
__device__ __forceinline__ void cp16(uint32_t dst, const void* src) {
    asm volatile("cp.async.cg.shared.global [%0], [%1], 16;" :: "r"(dst), "l"(src));
}
#define CP_COMMIT() asm volatile("cp.async.commit_group;" ::: "memory")
#define CP_WAIT(n)  asm volatile("cp.async.wait_group %0;" :: "n"(n) : "memory")

__device__ __forceinline__ void ldsm_x4(uint32_t* r, uint32_t addr) {
    asm volatile("ldmatrix.sync.aligned.m8n8.x4.shared.b16 {%0,%1,%2,%3}, [%4];"
        : "=r"(r[0]), "=r"(r[1]), "=r"(r[2]), "=r"(r[3]) : "r"(addr));
}
__device__ __forceinline__ void ldsm_x2(uint32_t* r, uint32_t addr) {
    asm volatile("ldmatrix.sync.aligned.m8n8.x2.shared.b16 {%0,%1}, [%2];"
        : "=r"(r[0]), "=r"(r[1]) : "r"(addr));
}
__device__ __forceinline__ void mma_bf16(float* c, const uint32_t* a, const uint32_t* b) {
    asm volatile("mma.sync.aligned.m16n8k16.row.col.f32.bf16.bf16.f32 "
        "{%0,%1,%2,%3}, {%4,%5,%6,%7}, {%8,%9}, {%0,%1,%2,%3};"
        : "+f"(c[0]), "+f"(c[1]), "+f"(c[2]), "+f"(c[3])
        : "r"(a[0]), "r"(a[1]), "r"(a[2]), "r"(a[3]), "r"(b[0]), "r"(b[1]));
}

// ---------------- kernel 0: detect ids dtype + reset worklist ----------------
__global__ void detect_kernel(const unsigned int* __restrict__ w)
{
    __shared__ int s_any;
    if (threadIdx.x == 0) s_any = 0;
    __syncthreads();
    for (int i = 2 * threadIdx.x + 1; i < MROWS; i += 2 * blockDim.x)
        if (w[i] != 0u) s_any = 1;
    __syncthreads();
    if (threadIdx.x == 0) {
        g_ids_is64 = (s_any == 0) ? 1 : 0;
        g_wl_count = 0;
    }
}

// ---------------- kernel 1: pack n-gram codes ----------------
__global__ void prep_codes_kernel(const void* __restrict__ ids_raw,
                                  const int* __restrict__ n_ptr)
{
    int idx = blockIdx.x * blockDim.x + threadIdx.x;
    if (idx >= MROWS) return;
    int n = *n_ptr;
    int is64 = g_ids_is64;
    const int*       i32 = (const int*)ids_raw;
    const long long* i64 = (const long long*)ids_raw;
    int b = idx / LSEQ;
    int q = idx % LSEQ;
    unsigned long long code = 0ull;
    if (q >= n - 1) {
        for (int i = 0; i < n; i++) {
            int pos = b * LSEQ + (q - n + 1 + i);
            long long v = is64 ? i64[pos] : (long long)i32[pos];
            code = (code << 16) | (unsigned long long)(v & 0xFFFF);
        }
    }
    g_codes[idx] = code;
}

// ---------------- kernel 2: matches -> pooled rows + worklist ----------------
__global__ __launch_bounds__(256) void pool_kernel(const float* __restrict__ hidden)
{
    __shared__ int s_match[LSEQ];
    __shared__ int s_cnt;
    int blk = blockIdx.x;
    int tid = threadIdx.x;
    int b = blk / LSEQ;
    int q = blk % LSEQ;
    if (tid == 0) s_cnt = 0;
    __syncthreads();
    unsigned long long myc = g_codes[blk];
    for (int k = tid; k < q; k += 256) {
        if (g_codes[b * LSEQ + k] == myc) {
            int pos = atomicAdd(&s_cnt, 1);
            s_match[pos] = k;
        }
    }
    __syncthreads();
    int cnt = s_cnt;
    if (cnt == 0) return;
    if (tid == 0) {
        int wi = atomicAdd(&g_wl_count, 1);
        g_wl[wi] = blk;
    }
    int c = tid * 4;
    float4 acc = make_float4(0.f, 0.f, 0.f, 0.f);
    for (int m = 0; m < cnt; m++) {
        const float4 h = *(const float4*)&hidden[((size_t)b * LSEQ + s_match[m]) * DDIM + c];
        acc.x += h.x; acc.y += h.y; acc.z += h.z; acc.w += h.w;
    }
    float inv = 1.0f / (float)cnt;
    acc.x *= inv; acc.y *= inv; acc.z *= inv; acc.w *= inv;
    *(float4*)&g_pooled[(size_t)blk * DDIM + c] = acc;
}

// ---------------- kernel: fp32 -> bf16 hi/lo split (X and W1) ----------------
__global__ void convert_kernel(const float* __restrict__ srcA,
                               __nv_bfloat16* __restrict__ dAhi,
                               __nv_bfloat16* __restrict__ dAlo,
                               const float* __restrict__ srcB,
                               __nv_bfloat16* __restrict__ dBhi,
                               __nv_bfloat16* __restrict__ dBlo)
{
    const int A4 = MROWS * KDIM / 4;
    const int B4 = NCOLS * KDIM / 4;
    int gid = blockIdx.x * blockDim.x + threadIdx.x;
    int stride = gridDim.x * blockDim.x;
    for (int i = gid; i < A4 + B4; i += stride) {
        const float* src; __nv_bfloat16 *dhi, *dlo; int j;
        if (i < A4) { src = srcA; dhi = dAhi; dlo = dAlo; j = i; }
        else        { src = srcB; dhi = dBhi; dlo = dBlo; j = i - A4; }
        float4 v = ((const float4*)src)[j];
        __nv_bfloat16 h0 = __float2bfloat16_rn(v.x);
        __nv_bfloat16 h1 = __float2bfloat16_rn(v.y);
        __nv_bfloat16 h2 = __float2bfloat16_rn(v.z);
        __nv_bfloat16 h3 = __float2bfloat16_rn(v.w);
        __nv_bfloat16 l0 = __float2bfloat16_rn(v.x - __bfloat162float(h0));
        __nv_bfloat16 l1 = __float2bfloat16_rn(v.y - __bfloat162float(h1));
        __nv_bfloat16 l2 = __float2bfloat16_rn(v.z - __bfloat162float(h2));
        __nv_bfloat16 l3 = __float2bfloat16_rn(v.w - __bfloat162float(h3));
        ((__nv_bfloat162*)dhi)[2 * j + 0] = __nv_bfloat162(h0, h1);
        ((__nv_bfloat162*)dhi)[2 * j + 1] = __nv_bfloat162(h2, h3);
        ((__nv_bfloat162*)dlo)[2 * j + 0] = __nv_bfloat162(l0, l1);
        ((__nv_bfloat162*)dlo)[2 * j + 1] = __nv_bfloat162(l2, l3);
    }
}

// ---------------- kernel 3: HMMA split-bf16 GEMM  C = X@W1^T + b1 + b2 ----------------
// CTA 128x256, BK=64 (SW128 rows). 8 warps (2x4), warp tile 64x64.
// Inner loop j-blocked (4 cols of N=8) to cap live regs ~200 (no spills).
static constexpr int TBM = 128, TBN = 256, TBK = 64;
static constexpr int N_CHUNKS = KDIM / TBK;                      // 16
static constexpr int ST_AHI = 0, ST_ALO = 16384, ST_BHI = 32768, ST_BLO = 65536;
static constexpr int STAGE_BYTES = 98304;
static constexpr int SMEM_DYN = 1024 + 2 * STAGE_BYTES;

__global__ __launch_bounds__(256, 1)
void gemm_mma_kernel(const float* __restrict__ b1,
                     const float* __restrict__ b2,
                     float* __restrict__ C)
{
    extern __shared__ char smem[];
    uint32_t sbase = (smem_u32(smem) + 1023u) & ~1023u;

    int tid  = threadIdx.x;
    int wid  = tid >> 5;
    int lane = tid & 31;
    int row0 = blockIdx.y * TBM;
    int col0 = blockIdx.x * TBN;

    int wm = wid >> 2;            // 0..1
    int wn = wid & 3;             // 0..3
    int mbase = wm * 64;
    int nbase = wn * 64;

    int arow_l = (lane & 15);
    int aklane = (lane >> 4) * 16;
    uint32_t aoffs[4], axors[4];
#pragma unroll
    for (int i = 0; i < 4; i++) {
        int r = mbase + 16 * i + arow_l;
        aoffs[i] = (uint32_t)(r * 128);
        axors[i] = (uint32_t)((r & 7) << 4);
    }
    int brow_l = (lane & 7);
    int bklane = ((lane >> 3) & 1) * 16;
    uint32_t bxor = (uint32_t)(brow_l << 4);
    uint32_t boffs[8];
#pragma unroll
    for (int j = 0; j < 8; j++)
        boffs[j] = (uint32_t)((nbase + 8 * j + brow_l) * 128);

    float acc[4][8][4];
#pragma unroll
    for (int i = 0; i < 4; i++)
#pragma unroll
        for (int j = 0; j < 8; j++)
#pragma unroll
            for (int t = 0; t < 4; t++) acc[i][j][t] = 0.f;

    auto load_chunk = [&](int c, uint32_t sb) {
        int k0 = c * TBK;
        for (int i = tid; i < 1024; i += 256) {        // A: 128 rows x 8 chunks
            int r = i >> 3, c16 = i & 7;
            uint32_t off = (uint32_t)(r * 128 + c16 * 16) ^ (uint32_t)((r & 7) << 4);
            size_t src = (size_t)(row0 + r) * KDIM + k0 + c16 * 8;
            cp16(sb + ST_AHI + off, &g_Ahi[src]);
            cp16(sb + ST_ALO + off, &g_Alo[src]);
        }
        for (int i = tid; i < 2048; i += 256) {        // B: 256 rows x 8 chunks
            int r = i >> 3, c16 = i & 7;
            uint32_t off = (uint32_t)(r * 128 + c16 * 16) ^ (uint32_t)((r & 7) << 4);
            size_t src = (size_t)(col0 + r) * KDIM + k0 + c16 * 8;
            cp16(sb + ST_BHI + off, &g_Bhi[src]);
            cp16(sb + ST_BLO + off, &g_Blo[src]);
        }
        CP_COMMIT();
    };

    load_chunk(0, sbase);

#pragma unroll 1
    for (int c = 0; c < N_CHUNKS; c++) {
        uint32_t sb = sbase + (uint32_t)(c & 1) * STAGE_BYTES;
        if (c + 1 < N_CHUNKS) {
            load_chunk(c + 1, sbase + (uint32_t)((c + 1) & 1) * STAGE_BYTES);
            CP_WAIT(1);
        } else {
            CP_WAIT(0);
        }
        __syncthreads();

#pragma unroll
        for (int ks = 0; ks < 4; ks++) {
            uint32_t kb = (uint32_t)(ks * 32);
            uint32_t akcol = kb + (uint32_t)aklane;
            uint32_t bkcol = kb + (uint32_t)bklane;

            uint32_t ahi[4][4], alo[4][4];
#pragma unroll
            for (int i = 0; i < 4; i++)
                ldsm_x4(ahi[i], sb + ST_AHI + aoffs[i] + (akcol ^ axors[i]));
#pragma unroll
            for (int i = 0; i < 4; i++)
                ldsm_x4(alo[i], sb + ST_ALO + aoffs[i] + (akcol ^ axors[i]));

#pragma unroll
            for (int jb = 0; jb < 2; jb++) {
                uint32_t bhi[4][2], blo[4][2];
#pragma unroll
                for (int j = 0; j < 4; j++) {
                    ldsm_x2(bhi[j], sb + ST_BHI + boffs[jb * 4 + j] + (bkcol ^ bxor));
                    ldsm_x2(blo[j], sb + ST_BLO + boffs[jb * 4 + j] + (bkcol ^ bxor));
                }
#pragma unroll
                for (int i = 0; i < 4; i++)
#pragma unroll
                    for (int j = 0; j < 4; j++)
                        mma_bf16(acc[i][jb * 4 + j], ahi[i], bhi[j]);
#pragma unroll
                for (int i = 0; i < 4; i++)
#pragma unroll
                    for (int j = 0; j < 4; j++)
                        mma_bf16(acc[i][jb * 4 + j], alo[i], bhi[j]);
#pragma unroll
                for (int i = 0; i < 4; i++)
#pragma unroll
                    for (int j = 0; j < 4; j++)
                        mma_bf16(acc[i][jb * 4 + j], ahi[i], blo[j]);
            }
        }
        __syncthreads();
    }

    // ---- epilogue: fused bias, register -> gmem ----
    int quad = lane >> 2;
    int tq   = lane & 3;
#pragma unroll
    for (int j = 0; j < 8; j++) {
        int col = col0 + nbase + 8 * j + tq * 2;
        float2 s1 = *(const float2*)&b1[col];
        float2 s2 = *(const float2*)&b2[col];
        float bx = s1.x + s2.x, by = s1.y + s2.y;
#pragma unroll
        for (int i = 0; i < 4; i++) {
            int r0 = row0 + mbase + 16 * i + quad;
            *(float2*)&C[(size_t)r0 * NCOLS + col] =
                make_float2(acc[i][j][0] + bx, acc[i][j][1] + by);
            *(float2*)&C[(size_t)(r0 + 8) * NCOLS + col] =
                make_float2(acc[i][j][2] + bx, acc[i][j][3] + by);
        }
    }
}

// ---------------- kernel 4: sparse fixup  out[row] += pooled[row] @ W2^T ----------------
__global__ __launch_bounds__(256) void fixup_kernel(const float* __restrict__ W2,
                                                    float* __restrict__ C)
{
    int slot = blockIdx.x;
    if (slot >= g_wl_count) return;
    int row = g_wl[slot];

    __shared__ float s_x[DDIM];
    int tid = threadIdx.x;
    for (int d = tid; d < DDIM; d += 256) s_x[d] = g_pooled[(size_t)row * DDIM + d];
    __syncthreads();

    int warp = tid / 32;
    int lane = tid % 32;
    for (int j = warp * 128; j < warp * 128 + 128; j++) {
        const float* wrow = &W2[(size_t)j * KDIM];
        float sum = 0.f;
        for (int d = lane; d < KDIM; d += 32) sum += s_x[d] * wrow[d];
#pragma unroll
        for (int off = 16; off > 0; off >>= 1)
            sum += __shfl_down_sync(0xFFFFFFFFu, sum, off);
        if (lane == 0) C[(size_t)row * NCOLS + j] += sum;
    }
}

// ---------------- launch ----------------
extern "C" void kernel_launch(void* const* d_in, const int* in_sizes, int n_in,
                              void* d_out, int out_size)
{
    const float* hidden = (const float*)d_in[0];
    const void*  ids    = d_in[1];
    const float* W1     = (const float*)d_in[2];
    const float* b1     = (const float*)d_in[3];
    const float* W2     = (const float*)d_in[4];
    const float* b2     = (const float*)d_in[5];
    const int*   n_ptr  = (const int*)d_in[6];
    float*       out    = (float*)d_out;

    static bool attr_done = false;
    if (!attr_done) {
        cudaFuncSetAttribute(gemm_mma_kernel,
                             cudaFuncAttributeMaxDynamicSharedMemorySize, SMEM_DYN);
        attr_done = true;
    }

    void *pAhi, *pAlo, *pBhi, *pBlo;
    cudaGetSymbolAddress(&pAhi, g_Ahi);
    cudaGetSymbolAddress(&pAlo, g_Alo);
    cudaGetSymbolAddress(&pBhi, g_Bhi);
    cudaGetSymbolAddress(&pBlo, g_Blo);

    // Order chosen so the ncu -s 5 -c 1 window is likely to land on the GEMM.
    convert_kernel<<<2304, 256>>>(hidden, (__nv_bfloat16*)pAhi, (__nv_bfloat16*)pAlo,
                                  W1, (__nv_bfloat16*)pBhi, (__nv_bfloat16*)pBlo);
    detect_kernel<<<1, 1024>>>((const unsigned int*)ids);
    prep_codes_kernel<<<(MROWS + 255) / 256, 256>>>(ids, n_ptr);
    dim3 ggrid(NCOLS / TBN, MROWS / TBM);   // (4, 64)
    gemm_mma_kernel<<<ggrid, 256, SMEM_DYN>>>(b1, b2, out);
    pool_kernel<<<MROWS, 256>>>(hidden);
    fixup_kernel<<<MROWS, 256>>>(W2, out);
}

// round 7
// speedup vs baseline: 2.7143x; 2.4552x over previous
#include <cuda_runtime.h>
#include <cuda_fp16.h>
#include <cuda_bf16.h>
#include <cstdint>

// out [4,2048,1024] f32 = X@W1^T + b1 + pooled@W2^T + b2
// Main GEMM: plain fp16 mma.sync (m16n8k16, fp32 accum). fp16 rounding gives
// rel_err ~2e-4 << 1e-3 threshold. Legacy mma path is ~quarter-rate on sm_100,
// so minimizing MMA count (1 term vs 3) is the dominant lever.
// Sparse ngram-pooling correction stays exact fp32 (fixup_kernel).

static constexpr int BATCH = 4;
static constexpr int LSEQ  = 2048;
static constexpr int DDIM  = 1024;
static constexpr int MROWS = BATCH * LSEQ;   // 8192
static constexpr int NCOLS = DDIM;
static constexpr int KDIM  = DDIM;

// ---------------- device scratch ----------------
__device__ unsigned long long g_codes[MROWS];
__device__ float g_pooled[(size_t)MROWS * DDIM];
__device__ int g_wl[MROWS];
__device__ int g_wl_count;
__device__ int g_ids_is64;
__device__ __align__(256) __half g_Ah[(size_t)MROWS * KDIM];   // 16MB
__device__ __align__(256) __half g_Bh[(size_t)NCOLS * KDIM];   // 2MB

// ====================== PTX helpers (sm_80+ portable) ======================
__device__ __forceinline__ uint32_t smem_u32(const void* p) {
    uint32_t a;
    asm("{ .reg .u64 t; cvta.to.shared.u64 t, %1; cvt.u32.u64 %0, t; }" : "=r"(a) : "l"(p));
    return a;
}
__device__ __forceinline__ void cp16(uint32_t dst, const void* src) {
    asm volatile("cp.async.cg.shared.global [%0], [%1], 16;" :: "r"(dst), "l"(src));
}
#define CP_COMMIT() asm volatile("cp.async.commit_group;" ::: "memory")
#define CP_WAIT(n)  asm volatile("cp.async.wait_group %0;" :: "n"(n) : "memory")

__device__ __forceinline__ void ldsm_x4(uint32_t* r, uint32_t addr) {
    asm volatile("ldmatrix.sync.aligned.m8n8.x4.shared.b16 {%0,%1,%2,%3}, [%4];"
        : "=r"(r[0]), "=r"(r[1]), "=r"(r[2]), "=r"(r[3]) : "r"(addr));
}
__device__ __forceinline__ void ldsm_x2(uint32_t* r, uint32_t addr) {
    asm volatile("ldmatrix.sync.aligned.m8n8.x2.shared.b16 {%0,%1}, [%2];"
        : "=r"(r[0]), "=r"(r[1]) : "r"(addr));
}
__device__ __forceinline__ void mma_f16(float* c, const uint32_t* a, const uint32_t* b) {
    asm volatile("mma.sync.aligned.m16n8k16.row.col.f32.f16.f16.f32 "
        "{%0,%1,%2,%3}, {%4,%5,%6,%7}, {%8,%9}, {%0,%1,%2,%3};"
        : "+f"(c[0]), "+f"(c[1]), "+f"(c[2]), "+f"(c[3])
        : "r"(a[0]), "r"(a[1]), "r"(a[2]), "r"(a[3]), "r"(b[0]), "r"(b[1]));
}

// ---------------- kernel 0: detect ids dtype + reset worklist ----------------
__global__ void detect_kernel(const unsigned int* __restrict__ w)
{
    __shared__ int s_any;
    if (threadIdx.x == 0) s_any = 0;
    __syncthreads();
    for (int i = 2 * threadIdx.x + 1; i < MROWS; i += 2 * blockDim.x)
        if (w[i] != 0u) s_any = 1;
    __syncthreads();
    if (threadIdx.x == 0) {
        g_ids_is64 = (s_any == 0) ? 1 : 0;
        g_wl_count = 0;
    }
}

// ---------------- kernel 1: pack n-gram codes ----------------
__global__ void prep_codes_kernel(const void* __restrict__ ids_raw,
                                  const int* __restrict__ n_ptr)
{
    int idx = blockIdx.x * blockDim.x + threadIdx.x;
    if (idx >= MROWS) return;
    int n = *n_ptr;
    int is64 = g_ids_is64;
    const int*       i32 = (const int*)ids_raw;
    const long long* i64 = (const long long*)ids_raw;
    int b = idx / LSEQ;
    int q = idx % LSEQ;
    unsigned long long code = 0ull;
    if (q >= n - 1) {
        for (int i = 0; i < n; i++) {
            int pos = b * LSEQ + (q - n + 1 + i);
            long long v = is64 ? i64[pos] : (long long)i32[pos];
            code = (code << 16) | (unsigned long long)(v & 0xFFFF);
        }
    }
    g_codes[idx] = code;
}

// ---------------- kernel 2: matches -> pooled rows + worklist ----------------
__global__ __launch_bounds__(256) void pool_kernel(const float* __restrict__ hidden)
{
    __shared__ int s_match[LSEQ];
    __shared__ int s_cnt;
    int blk = blockIdx.x;
    int tid = threadIdx.x;
    int b = blk / LSEQ;
    int q = blk % LSEQ;
    if (tid == 0) s_cnt = 0;
    __syncthreads();
    unsigned long long myc = g_codes[blk];
    for (int k = tid; k < q; k += 256) {
        if (g_codes[b * LSEQ + k] == myc) {
            int pos = atomicAdd(&s_cnt, 1);
            s_match[pos] = k;
        }
    }
    __syncthreads();
    int cnt = s_cnt;
    if (cnt == 0) return;
    if (tid == 0) {
        int wi = atomicAdd(&g_wl_count, 1);
        g_wl[wi] = blk;
    }
    int c = tid * 4;
    float4 acc = make_float4(0.f, 0.f, 0.f, 0.f);
    for (int m = 0; m < cnt; m++) {
        const float4 h = *(const float4*)&hidden[((size_t)b * LSEQ + s_match[m]) * DDIM + c];
        acc.x += h.x; acc.y += h.y; acc.z += h.z; acc.w += h.w;
    }
    float inv = 1.0f / (float)cnt;
    acc.x *= inv; acc.y *= inv; acc.z *= inv; acc.w *= inv;
    *(float4*)&g_pooled[(size_t)blk * DDIM + c] = acc;
}

// ---------------- kernel: fp32 -> fp16 convert (X and W1) ----------------
__global__ void convert_kernel(const float* __restrict__ srcA,
                               __half* __restrict__ dA,
                               const float* __restrict__ srcB,
                               __half* __restrict__ dB)
{
    const int A4 = MROWS * KDIM / 4;
    const int B4 = NCOLS * KDIM / 4;
    int gid = blockIdx.x * blockDim.x + threadIdx.x;
    int stride = gridDim.x * blockDim.x;
    for (int i = gid; i < A4 + B4; i += stride) {
        const float* src; __half* dst; int j;
        if (i < A4) { src = srcA; dst = dA; j = i; }
        else        { src = srcB; dst = dB; j = i - A4; }
        float4 v = ((const float4*)src)[j];
        __half2 h01 = __floats2half2_rn(v.x, v.y);
        __half2 h23 = __floats2half2_rn(v.z, v.w);
        ((__half2*)dst)[2 * j + 0] = h01;
        ((__half2*)dst)[2 * j + 1] = h23;
    }
}

// ---------------- kernel 3: fp16 HMMA GEMM  C = X@W1^T + b1 + b2 ----------------
// CTA 128x256, BK=64 (128B SW128 rows). 8 warps (2x4), warp tile 64x64.
// 4-stage cp.async pipeline (48KB/stage, 192KB total).
static constexpr int TBM = 128, TBN = 256, TBK = 64;
static constexpr int N_CHUNKS = KDIM / TBK;                      // 16
static constexpr int ST_AH = 0, ST_BH = 16384;
static constexpr int STAGE_BYTES = 49152;                        // 48KB
static constexpr int N_STAGES = 4;
static constexpr int SMEM_DYN = 1024 + N_STAGES * STAGE_BYTES;   // ~193KB

__global__ __launch_bounds__(256, 1)
void gemm_mma_kernel(const float* __restrict__ b1,
                     const float* __restrict__ b2,
                     float* __restrict__ C)
{
    extern __shared__ char smem[];
    uint32_t sbase = (smem_u32(smem) + 1023u) & ~1023u;

    int tid  = threadIdx.x;
    int wid  = tid >> 5;
    int lane = tid & 31;
    int row0 = blockIdx.y * TBM;
    int col0 = blockIdx.x * TBN;

    int wm = wid >> 2;            // 0..1
    int wn = wid & 3;             // 0..3
    int mbase = wm * 64;
    int nbase = wn * 64;

    int arow_l = (lane & 15);
    int aklane = (lane >> 4) * 16;
    uint32_t aoffs[4], axors[4];
#pragma unroll
    for (int i = 0; i < 4; i++) {
        int r = mbase + 16 * i + arow_l;
        aoffs[i] = (uint32_t)(r * 128);
        axors[i] = (uint32_t)((r & 7) << 4);
    }
    int brow_l = (lane & 7);
    int bklane = ((lane >> 3) & 1) * 16;
    uint32_t bxor = (uint32_t)(brow_l << 4);
    uint32_t boffs[8];
#pragma unroll
    for (int j = 0; j < 8; j++)
        boffs[j] = (uint32_t)((nbase + 8 * j + brow_l) * 128);

    float acc[4][8][4];
#pragma unroll
    for (int i = 0; i < 4; i++)
#pragma unroll
        for (int j = 0; j < 8; j++)
#pragma unroll
            for (int t = 0; t < 4; t++) acc[i][j][t] = 0.f;

    auto load_chunk = [&](int c) {
        uint32_t sb = sbase + (uint32_t)(c & (N_STAGES - 1)) * STAGE_BYTES;
        int k0 = c * TBK;
        for (int i = tid; i < 1024; i += 256) {        // A: 128 rows x 8x16B
            int r = i >> 3, c16 = i & 7;
            uint32_t off = (uint32_t)(r * 128 + c16 * 16) ^ (uint32_t)((r & 7) << 4);
            cp16(sb + ST_AH + off, &g_Ah[(size_t)(row0 + r) * KDIM + k0 + c16 * 8]);
        }
        for (int i = tid; i < 2048; i += 256) {        // B: 256 rows x 8x16B
            int r = i >> 3, c16 = i & 7;
            uint32_t off = (uint32_t)(r * 128 + c16 * 16) ^ (uint32_t)((r & 7) << 4);
            cp16(sb + ST_BH + off, &g_Bh[(size_t)(col0 + r) * KDIM + k0 + c16 * 8]);
        }
        CP_COMMIT();
    };

    load_chunk(0);
    load_chunk(1);
    load_chunk(2);

#pragma unroll 1
    for (int c = 0; c < N_CHUNKS; c++) {
        // wait until stage c is resident
        if (c <= N_CHUNKS - 3)      CP_WAIT(2);
        else if (c == N_CHUNKS - 2) CP_WAIT(1);
        else                        CP_WAIT(0);
        __syncthreads();            // visibility + all warps done with stage (c-1)

        if (c + 3 < N_CHUNKS) load_chunk(c + 3);   // refills stage (c-1)&3 — safe

        uint32_t sb = sbase + (uint32_t)(c & (N_STAGES - 1)) * STAGE_BYTES;
#pragma unroll
        for (int ks = 0; ks < 4; ks++) {
            uint32_t kb = (uint32_t)(ks * 32);
            uint32_t akcol = kb + (uint32_t)aklane;
            uint32_t bkcol = kb + (uint32_t)bklane;

            uint32_t af[4][4], bf[8][2];
#pragma unroll
            for (int i = 0; i < 4; i++)
                ldsm_x4(af[i], sb + ST_AH + aoffs[i] + (akcol ^ axors[i]));
#pragma unroll
            for (int j = 0; j < 8; j++)
                ldsm_x2(bf[j], sb + ST_BH + boffs[j] + (bkcol ^ bxor));
#pragma unroll
            for (int i = 0; i < 4; i++)
#pragma unroll
                for (int j = 0; j < 8; j++)
                    mma_f16(acc[i][j], af[i], bf[j]);
        }
    }

    // ---- epilogue: fused bias, register -> gmem ----
    int quad = lane >> 2;
    int tq   = lane & 3;
#pragma unroll
    for (int j = 0; j < 8; j++) {
        int col = col0 + nbase + 8 * j + tq * 2;
        float2 s1 = *(const float2*)&b1[col];
        float2 s2 = *(const float2*)&b2[col];
        float bx = s1.x + s2.x, by = s1.y + s2.y;
#pragma unroll
        for (int i = 0; i < 4; i++) {
            int r0 = row0 + mbase + 16 * i + quad;
            *(float2*)&C[(size_t)r0 * NCOLS + col] =
                make_float2(acc[i][j][0] + bx, acc[i][j][1] + by);
            *(float2*)&C[(size_t)(r0 + 8) * NCOLS + col] =
                make_float2(acc[i][j][2] + bx, acc[i][j][3] + by);
        }
    }
}

// ---------------- kernel 4: sparse fixup  out[row] += pooled[row] @ W2^T ----------------
// grid (64, 8): blockIdx.x strides the worklist, blockIdx.y picks a 128-col slice.
// Fully-unrolled 32-load dots for high MLP (W2 is L2-resident after first touch).
__global__ __launch_bounds__(256) void fixup_kernel(const float* __restrict__ W2,
                                                    float* __restrict__ C)
{
    __shared__ float s_x[DDIM];
    int cnt = g_wl_count;
    int tid  = threadIdx.x;
    int warp = tid >> 5;
    int lane = tid & 31;
    int colbase = blockIdx.y * 128;

    for (int slot = blockIdx.x; slot < cnt; slot += 64) {
        int row = g_wl[slot];
        for (int d = tid; d < DDIM; d += 256)
            s_x[d] = g_pooled[(size_t)row * DDIM + d];
        __syncthreads();

        // each warp: 16 columns
        for (int jj = 0; jj < 16; jj++) {
            int j = colbase + warp * 16 + jj;
            const float* wrow = &W2[(size_t)j * KDIM + lane];
            float sum = 0.f;
#pragma unroll
            for (int d = 0; d < KDIM / 32; d++)
                sum += s_x[lane + d * 32] * wrow[d * 32];
#pragma unroll
            for (int off = 16; off > 0; off >>= 1)
                sum += __shfl_down_sync(0xFFFFFFFFu, sum, off);
            if (lane == 0) C[(size_t)row * NCOLS + j] += sum;
        }
        __syncthreads();   // done with s_x before next slot overwrites it
    }
}

// ---------------- launch ----------------
extern "C" void kernel_launch(void* const* d_in, const int* in_sizes, int n_in,
                              void* d_out, int out_size)
{
    const float* hidden = (const float*)d_in[0];
    const void*  ids    = d_in[1];
    const float* W1     = (const float*)d_in[2];
    const float* b1     = (const float*)d_in[3];
    const float* W2     = (const float*)d_in[4];
    const float* b2     = (const float*)d_in[5];
    const int*   n_ptr  = (const int*)d_in[6];
    float*       out    = (float*)d_out;

    static bool attr_done = false;
    if (!attr_done) {
        cudaFuncSetAttribute(gemm_mma_kernel,
                             cudaFuncAttributeMaxDynamicSharedMemorySize, SMEM_DYN);
        attr_done = true;
    }

    void *pAh, *pBh;
    cudaGetSymbolAddress(&pAh, g_Ah);
    cudaGetSymbolAddress(&pBh, g_Bh);

    convert_kernel<<<2304, 256>>>(hidden, (__half*)pAh, W1, (__half*)pBh);
    detect_kernel<<<1, 1024>>>((const unsigned int*)ids);
    prep_codes_kernel<<<(MROWS + 255) / 256, 256>>>(ids, n_ptr);
    dim3 ggrid(NCOLS / TBN, MROWS / TBM);   // (4, 64)
    gemm_mma_kernel<<<ggrid, 256, SMEM_DYN>>>(b1, b2, out);   // launch #4 for ncu
    pool_kernel<<<MROWS, 256>>>(hidden);
    dim3 fgrid(64, 8);
    fixup_kernel<<<fgrid, 256>>>(W2, out);
}

// round 9
// speedup vs baseline: 2.7809x; 1.0245x over previous
#include <cuda_runtime.h>
#include <cuda_fp16.h>
#include <cuda_bf16.h>
#include <cstdint>

// out [4,2048,1024] f32 = X@W1^T + b1 + pooled@W2^T + b2
// GEMM: fp16 mma.sync m16n8k16 (fp32 accum), register-double-buffered fragments.
// Sparse ngram pooling correction stays exact fp32.

static constexpr int BATCH = 4;
static constexpr int LSEQ  = 2048;
static constexpr int DDIM  = 1024;
static constexpr int MROWS = BATCH * LSEQ;   // 8192
static constexpr int NCOLS = DDIM;
static constexpr int KDIM  = DDIM;

// ---------------- device scratch ----------------
__device__ unsigned long long g_codes[MROWS];
__device__ float g_pooled[(size_t)MROWS * DDIM];
__device__ int g_wl[MROWS];
__device__ int g_wl_count;
__device__ int g_ids_is64;
__device__ __align__(256) __half g_Ah[(size_t)MROWS * KDIM];   // 16MB
__device__ __align__(256) __half g_Bh[(size_t)NCOLS * KDIM];   // 2MB

// ====================== PTX helpers (sm_80+ portable) ======================
__device__ __forceinline__ uint32_t smem_u32(const void* p) {
    uint32_t a;
    asm("{ .reg .u64 t; cvta.to.shared.u64 t, %1; cvt.u32.u64 %0, t; }" : "=r"(a) : "l"(p));
    return a;
}
__device__ __forceinline__ void cp16(uint32_t dst, const void* src) {
    asm volatile("cp.async.cg.shared.global [%0], [%1], 16;" :: "r"(dst), "l"(src));
}
#define CP_COMMIT() asm volatile("cp.async.commit_group;" ::: "memory")
#define CP_WAIT(n)  asm volatile("cp.async.wait_group %0;" :: "n"(n) : "memory")

__device__ __forceinline__ void ldsm_x4(uint32_t* r, uint32_t addr) {
    asm volatile("ldmatrix.sync.aligned.m8n8.x4.shared.b16 {%0,%1,%2,%3}, [%4];"
        : "=r"(r[0]), "=r"(r[1]), "=r"(r[2]), "=r"(r[3]) : "r"(addr));
}
__device__ __forceinline__ void mma_f16(float* c, const uint32_t* a, const uint32_t* b) {
    asm volatile("mma.sync.aligned.m16n8k16.row.col.f32.f16.f16.f32 "
        "{%0,%1,%2,%3}, {%4,%5,%6,%7}, {%8,%9}, {%0,%1,%2,%3};"
        : "+f"(c[0]), "+f"(c[1]), "+f"(c[2]), "+f"(c[3])
        : "r"(a[0]), "r"(a[1]), "r"(a[2]), "r"(a[3]), "r"(b[0]), "r"(b[1]));
}
__device__ __forceinline__ uint32_t pack2h(float x, float y) {
    union { __half2 h; uint32_t u; } cvt;
    cvt.h = __floats2half2_rn(x, y);
    return cvt.u;
}

// ---------------- kernel 0: detect ids dtype + reset worklist ----------------
__global__ void detect_kernel(const unsigned int* __restrict__ w)
{
    __shared__ int s_any;
    if (threadIdx.x == 0) s_any = 0;
    __syncthreads();
    for (int i = 2 * threadIdx.x + 1; i < MROWS; i += 2 * blockDim.x)
        if (w[i] != 0u) s_any = 1;
    __syncthreads();
    if (threadIdx.x == 0) {
        g_ids_is64 = (s_any == 0) ? 1 : 0;
        g_wl_count = 0;
    }
}

// ---------------- kernel 1: pack n-gram codes ----------------
__global__ void prep_codes_kernel(const void* __restrict__ ids_raw,
                                  const int* __restrict__ n_ptr)
{
    int idx = blockIdx.x * blockDim.x + threadIdx.x;
    if (idx >= MROWS) return;
    int n = *n_ptr;
    int is64 = g_ids_is64;
    const int*       i32 = (const int*)ids_raw;
    const long long* i64 = (const long long*)ids_raw;
    int b = idx / LSEQ;
    int q = idx % LSEQ;
    unsigned long long code = 0ull;
    if (q >= n - 1) {
        for (int i = 0; i < n; i++) {
            int pos = b * LSEQ + (q - n + 1 + i);
            long long v = is64 ? i64[pos] : (long long)i32[pos];
            code = (code << 16) | (unsigned long long)(v & 0xFFFF);
        }
    }
    g_codes[idx] = code;
}

// ---------------- kernel 2: matches -> pooled rows + worklist ----------------
__global__ __launch_bounds__(256) void pool_kernel(const float* __restrict__ hidden)
{
    __shared__ int s_match[LSEQ];
    __shared__ int s_cnt;
    int blk = blockIdx.x;
    int tid = threadIdx.x;
    int b = blk / LSEQ;
    int q = blk % LSEQ;
    if (tid == 0) s_cnt = 0;
    __syncthreads();
    unsigned long long myc = g_codes[blk];
    for (int k = tid; k < q; k += 256) {
        if (g_codes[b * LSEQ + k] == myc) {
            int pos = atomicAdd(&s_cnt, 1);
            s_match[pos] = k;
        }
    }
    __syncthreads();
    int cnt = s_cnt;
    if (cnt == 0) return;
    if (tid == 0) {
        int wi = atomicAdd(&g_wl_count, 1);
        g_wl[wi] = blk;
    }
    int c = tid * 4;
    float4 acc = make_float4(0.f, 0.f, 0.f, 0.f);
    for (int m = 0; m < cnt; m++) {
        const float4 h = *(const float4*)&hidden[((size_t)b * LSEQ + s_match[m]) * DDIM + c];
        acc.x += h.x; acc.y += h.y; acc.z += h.z; acc.w += h.w;
    }
    float inv = 1.0f / (float)cnt;
    acc.x *= inv; acc.y *= inv; acc.z *= inv; acc.w *= inv;
    *(float4*)&g_pooled[(size_t)blk * DDIM + c] = acc;
}

// ---------------- kernel: fp32 -> fp16 convert (exact tiling, branch-free) ----------------
// grid 512 x 256 = 131072 threads. A = 1048576 32B-units (8/thread), B = 131072 (1/thread).
__global__ __launch_bounds__(256) void convert_kernel(const float4* __restrict__ srcA,
                                                      uint4* __restrict__ dA,
                                                      const float4* __restrict__ srcB,
                                                      uint4* __restrict__ dB)
{
    const int T = 131072;
    int t = blockIdx.x * 256 + threadIdx.x;
#pragma unroll
    for (int it = 0; it < 8; it++) {
        int u = t + it * T;
        float4 v0 = srcA[2 * u];
        float4 v1 = srcA[2 * u + 1];
        uint4 o;
        o.x = pack2h(v0.x, v0.y);
        o.y = pack2h(v0.z, v0.w);
        o.z = pack2h(v1.x, v1.y);
        o.w = pack2h(v1.z, v1.w);
        dA[u] = o;
    }
    {
        int u = t;
        float4 v0 = srcB[2 * u];
        float4 v1 = srcB[2 * u + 1];
        uint4 o;
        o.x = pack2h(v0.x, v0.y);
        o.y = pack2h(v0.z, v0.w);
        o.z = pack2h(v1.x, v1.y);
        o.w = pack2h(v1.z, v1.w);
        dB[u] = o;
    }
}

// ---------------- kernel 3: fp16 HMMA GEMM  C = X@W1^T + b1 + b2 ----------------
// CTA 128x256, BK=64 (128B SW128 rows), 8 warps (2x4), warp tile 64x64.
// 4-stage cp.async pipeline + register double-buffered fragments.
static constexpr int TBM = 128, TBN = 256, TBK = 64;
static constexpr int N_CHUNKS = KDIM / TBK;                      // 16
static constexpr int ST_AH = 0, ST_BH = 16384;
static constexpr int STAGE_BYTES = 49152;                        // 48KB
static constexpr int N_STAGES = 4;
static constexpr int SMEM_DYN = 1024 + N_STAGES * STAGE_BYTES;

__global__ __launch_bounds__(256, 1)
void gemm_mma_kernel(const float* __restrict__ b1,
                     const float* __restrict__ b2,
                     float* __restrict__ C)
{
    extern __shared__ char smem[];
    uint32_t sbase = (smem_u32(smem) + 1023u) & ~1023u;

    int tid  = threadIdx.x;
    int wid  = tid >> 5;
    int lane = tid & 31;
    int row0 = blockIdx.y * TBM;
    int col0 = blockIdx.x * TBN;

    int wm = wid >> 2;            // 0..1
    int wn = wid & 3;             // 0..3
    int mbase = wm * 64;
    int nbase = wn * 64;

    // A ldmatrix addressing (x4: 16 rows x 2 k-halves via lane>>4)
    int arow_l = (lane & 15);
    int aklane = (lane >> 4) * 16;
    uint32_t aoffs[4], axors[4];
#pragma unroll
    for (int i = 0; i < 4; i++) {
        int r = mbase + 16 * i + arow_l;
        aoffs[i] = (uint32_t)(r * 128);
        axors[i] = (uint32_t)((r & 7) << 4);
    }
    // B ldmatrix addressing (x4 covers TWO n8 tiles: lanes 0-15 tile 2j, 16-31 tile 2j+1)
    int btile_l = lane >> 4;              // 0..1
    int brow_l  = lane & 7;
    int bkhalf16 = ((lane >> 3) & 1) * 16;
    uint32_t bxor = (uint32_t)(brow_l << 4);
    uint32_t boffs4[4];
#pragma unroll
    for (int jp = 0; jp < 4; jp++)
        boffs4[jp] = (uint32_t)((nbase + 8 * (2 * jp + btile_l) + brow_l) * 128);

    float acc[4][8][4];
#pragma unroll
    for (int i = 0; i < 4; i++)
#pragma unroll
        for (int j = 0; j < 8; j++)
#pragma unroll
            for (int t = 0; t < 4; t++) acc[i][j][t] = 0.f;

    auto load_chunk = [&](int c) {
        uint32_t sb = sbase + (uint32_t)(c & (N_STAGES - 1)) * STAGE_BYTES;
        int k0 = c * TBK;
        for (int i = tid; i < 1024; i += 256) {
            int r = i >> 3, c16 = i & 7;
            uint32_t off = (uint32_t)(r * 128 + c16 * 16) ^ (uint32_t)((r & 7) << 4);
            cp16(sb + ST_AH + off, &g_Ah[(size_t)(row0 + r) * KDIM + k0 + c16 * 8]);
        }
        for (int i = tid; i < 2048; i += 256) {
            int r = i >> 3, c16 = i & 7;
            uint32_t off = (uint32_t)(r * 128 + c16 * 16) ^ (uint32_t)((r & 7) << 4);
            cp16(sb + ST_BH + off, &g_Bh[(size_t)(col0 + r) * KDIM + k0 + c16 * 8]);
        }
        CP_COMMIT();
    };

    uint32_t af[2][4][4], bf[2][8][2];

    auto load_frags = [&](uint32_t sb, int ks, int buf) {
        uint32_t kb = (uint32_t)(ks * 32);
        uint32_t akcol = kb + (uint32_t)aklane;
        uint32_t bkcol = kb + (uint32_t)bkhalf16;
#pragma unroll
        for (int i = 0; i < 4; i++)
            ldsm_x4(af[buf][i], sb + ST_AH + aoffs[i] + (akcol ^ axors[i]));
#pragma unroll
        for (int jp = 0; jp < 4; jp++)
            ldsm_x4(&bf[buf][2 * jp][0], sb + ST_BH + boffs4[jp] + (bkcol ^ bxor));
    };

    load_chunk(0);
    load_chunk(1);
    load_chunk(2);

#pragma unroll 1
    for (int c = 0; c < N_CHUNKS; c++) {
        if (c <= N_CHUNKS - 3)      CP_WAIT(2);
        else if (c == N_CHUNKS - 2) CP_WAIT(1);
        else                        CP_WAIT(0);
        __syncthreads();

        if (c + 3 < N_CHUNKS) load_chunk(c + 3);

        uint32_t sb = sbase + (uint32_t)(c & (N_STAGES - 1)) * STAGE_BYTES;
        load_frags(sb, 0, 0);
#pragma unroll
        for (int ks = 0; ks < 4; ks++) {
            int cur = ks & 1, nxt = cur ^ 1;
            if (ks < 3) load_frags(sb, ks + 1, nxt);
#pragma unroll
            for (int i = 0; i < 4; i++)
#pragma unroll
                for (int j = 0; j < 8; j++)
                    mma_f16(acc[i][j], af[cur][i], bf[cur][j]);
        }
    }

    // ---- epilogue: fused bias, register -> gmem ----
    int quad = lane >> 2;
    int tq   = lane & 3;
#pragma unroll
    for (int j = 0; j < 8; j++) {
        int col = col0 + nbase + 8 * j + tq * 2;
        float2 s1 = *(const float2*)&b1[col];
        float2 s2 = *(const float2*)&b2[col];
        float bx = s1.x + s2.x, by = s1.y + s2.y;
#pragma unroll
        for (int i = 0; i < 4; i++) {
            int r0 = row0 + mbase + 16 * i + quad;
            *(float2*)&C[(size_t)r0 * NCOLS + col] =
                make_float2(acc[i][j][0] + bx, acc[i][j][1] + by);
            *(float2*)&C[(size_t)(r0 + 8) * NCOLS + col] =
                make_float2(acc[i][j][2] + bx, acc[i][j][3] + by);
        }
    }
}

// ---------------- kernel 4: sparse fixup  out[row] += pooled[row] @ W2^T ----------------
__global__ __launch_bounds__(256) void fixup_kernel(const float* __restrict__ W2,
                                                    float* __restrict__ C)
{
    __shared__ float s_x[DDIM];
    int cnt = g_wl_count;
    int tid  = threadIdx.x;
    int warp = tid >> 5;
    int lane = tid & 31;
    int colbase = blockIdx.y * 128;

    for (int slot = blockIdx.x; slot < cnt; slot += 64) {
        int row = g_wl[slot];
        for (int d = tid; d < DDIM; d += 256)
            s_x[d] = g_pooled[(size_t)row * DDIM + d];
        __syncthreads();

        for (int jj = 0; jj < 16; jj++) {
            int j = colbase + warp * 16 + jj;
            const float* wrow = &W2[(size_t)j * KDIM + lane];
            float sum = 0.f;
#pragma unroll
            for (int d = 0; d < KDIM / 32; d++)
                sum += s_x[lane + d * 32] * wrow[d * 32];
#pragma unroll
            for (int off = 16; off > 0; off >>= 1)
                sum += __shfl_down_sync(0xFFFFFFFFu, sum, off);
            if (lane == 0) C[(size_t)row * NCOLS + j] += sum;
        }
        __syncthreads();
    }
}

// ---------------- launch ----------------
extern "C" void kernel_launch(void* const* d_in, const int* in_sizes, int n_in,
                              void* d_out, int out_size)
{
    const float* hidden = (const float*)d_in[0];
    const void*  ids    = d_in[1];
    const float* W1     = (const float*)d_in[2];
    const float* b1     = (const float*)d_in[3];
    const float* W2     = (const float*)d_in[4];
    const float* b2     = (const float*)d_in[5];
    const int*   n_ptr  = (const int*)d_in[6];
    float*       out    = (float*)d_out;

    static bool attr_done = false;
    if (!attr_done) {
        cudaFuncSetAttribute(gemm_mma_kernel,
                             cudaFuncAttributeMaxDynamicSharedMemorySize, SMEM_DYN);
        attr_done = true;
    }

    void *pAh, *pBh;
    cudaGetSymbolAddress(&pAh, g_Ah);
    cudaGetSymbolAddress(&pBh, g_Bh);

    convert_kernel<<<512, 256>>>((const float4*)hidden, (uint4*)pAh,
                                 (const float4*)W1, (uint4*)pBh);
    detect_kernel<<<1, 1024>>>((const unsigned int*)ids);
    prep_codes_kernel<<<(MROWS + 255) / 256, 256>>>(ids, n_ptr);
    dim3 ggrid(NCOLS / TBN, MROWS / TBM);   // (4, 64)
    gemm_mma_kernel<<<ggrid, 256, SMEM_DYN>>>(b1, b2, out);   // launch #4 for ncu
    pool_kernel<<<MROWS, 256>>>(hidden);
    dim3 fgrid(64, 8);
    fixup_kernel<<<fgrid, 256>>>(W2, out);
}

// round 10
// speedup vs baseline: 3.0414x; 1.0937x over previous
#include <cuda_runtime.h>
#include <cuda_fp16.h>
#include <cuda_bf16.h>
#include <cstdint>

// out [4,2048,1024] f32 = X@W1^T + b1 + pooled@W2^T + b2
// GEMM: fp16 mma.sync m16n8k16 (fp32 accum). Sparse ngram pooling in fp32.

static constexpr int BATCH = 4;
static constexpr int LSEQ  = 2048;
static constexpr int DDIM  = 1024;
static constexpr int MROWS = BATCH * LSEQ;   // 8192
static constexpr int NCOLS = DDIM;
static constexpr int KDIM  = DDIM;
static constexpr int NBUCK = 1 << 18;        // per-batch hash buckets

// ---------------- device scratch ----------------
__device__ unsigned long long g_codes[MROWS];
__device__ float g_pooled[(size_t)MROWS * DDIM];
__device__ int g_wl[MROWS];
__device__ int g_wl_count;
__device__ int g_ids_is64;
__device__ unsigned int g_cnt[BATCH * NBUCK];               // 4MB
__device__ __align__(256) __half g_Ah[(size_t)MROWS * KDIM];
__device__ __align__(256) __half g_Bh[(size_t)NCOLS * KDIM];

__device__ __forceinline__ uint32_t hash18(unsigned long long c) {
    return (uint32_t)(c ^ (c >> 18) ^ (c >> 36)) & (NBUCK - 1);
}

// ====================== PTX helpers (sm_80+ portable) ======================
__device__ __forceinline__ uint32_t smem_u32(const void* p) {
    uint32_t a;
    asm("{ .reg .u64 t; cvta.to.shared.u64 t, %1; cvt.u32.u64 %0, t; }" : "=r"(a) : "l"(p));
    return a;
}
__device__ __forceinline__ void cp16(uint32_t dst, const void* src) {
    asm volatile("cp.async.cg.shared.global [%0], [%1], 16;" :: "r"(dst), "l"(src));
}
#define CP_COMMIT() asm volatile("cp.async.commit_group;" ::: "memory")
#define CP_WAIT(n)  asm volatile("cp.async.wait_group %0;" :: "n"(n) : "memory")

__device__ __forceinline__ void ldsm_x4(uint32_t* r, uint32_t addr) {
    asm volatile("ldmatrix.sync.aligned.m8n8.x4.shared.b16 {%0,%1,%2,%3}, [%4];"
        : "=r"(r[0]), "=r"(r[1]), "=r"(r[2]), "=r"(r[3]) : "r"(addr));
}
__device__ __forceinline__ void mma_f16(float* c, const uint32_t* a, const uint32_t* b) {
    asm volatile("mma.sync.aligned.m16n8k16.row.col.f32.f16.f16.f32 "
        "{%0,%1,%2,%3}, {%4,%5,%6,%7}, {%8,%9}, {%0,%1,%2,%3};"
        : "+f"(c[0]), "+f"(c[1]), "+f"(c[2]), "+f"(c[3])
        : "r"(a[0]), "r"(a[1]), "r"(a[2]), "r"(a[3]), "r"(b[0]), "r"(b[1]));
}
__device__ __forceinline__ uint32_t pack2h(float x, float y) {
    union { __half2 h; uint32_t u; } cvt;
    cvt.h = __floats2half2_rn(x, y);
    return cvt.u;
}

// ---------------- kernel 0: detect ids dtype + zero counts + reset worklist ----------------
// grid 1024 x 256. All threads zero g_cnt (4 u32 each). Block 0 does detection.
__global__ __launch_bounds__(256) void detect_kernel(const unsigned int* __restrict__ w)
{
    int gid = blockIdx.x * 256 + threadIdx.x;
#pragma unroll
    for (int i = 0; i < 4; i++)
        g_cnt[gid + i * 262144] = 0u;

    if (blockIdx.x == 0) {
        __shared__ int s_any;
        if (threadIdx.x == 0) s_any = 0;
        __syncthreads();
        for (int i = 2 * threadIdx.x + 1; i < MROWS; i += 512)
            if (w[i] != 0u) s_any = 1;
        __syncthreads();
        if (threadIdx.x == 0) {
            g_ids_is64 = (s_any == 0) ? 1 : 0;
            g_wl_count = 0;
        }
    }
}

// ---------------- kernel 1: pack n-gram codes + bucket counts ----------------
__global__ void prep_codes_kernel(const void* __restrict__ ids_raw,
                                  const int* __restrict__ n_ptr)
{
    int idx = blockIdx.x * blockDim.x + threadIdx.x;
    if (idx >= MROWS) return;
    int n = *n_ptr;
    int is64 = g_ids_is64;
    const int*       i32 = (const int*)ids_raw;
    const long long* i64 = (const long long*)ids_raw;
    int b = idx / LSEQ;
    int q = idx % LSEQ;
    unsigned long long code = 0ull;
    if (q >= n - 1) {
        for (int i = 0; i < n; i++) {
            int pos = b * LSEQ + (q - n + 1 + i);
            long long v = is64 ? i64[pos] : (long long)i32[pos];
            code = (code << 16) | (unsigned long long)(v & 0xFFFF);
        }
    }
    g_codes[idx] = code;
    atomicAdd(&g_cnt[b * NBUCK + hash18(code)], 1u);
}

// ---------------- kernel 2: matches -> pooled rows + worklist (bucket-gated) ----------------
__global__ __launch_bounds__(256) void pool_kernel(const float* __restrict__ hidden)
{
    int blk = blockIdx.x;
    int tid = threadIdx.x;
    int b = blk / LSEQ;
    int q = blk % LSEQ;
    if (q == 0) return;
    unsigned long long myc = g_codes[blk];
    if (g_cnt[b * NBUCK + hash18(myc)] < 2u) return;   // no possible match

    __shared__ int s_match[LSEQ];
    __shared__ int s_cnt;
    if (tid == 0) s_cnt = 0;
    __syncthreads();
    for (int k = tid; k < q; k += 256) {
        if (g_codes[b * LSEQ + k] == myc) {
            int pos = atomicAdd(&s_cnt, 1);
            s_match[pos] = k;
        }
    }
    __syncthreads();
    int cnt = s_cnt;
    if (cnt == 0) return;
    if (tid == 0) {
        int wi = atomicAdd(&g_wl_count, 1);
        g_wl[wi] = blk;
    }
    int c = tid * 4;
    float4 acc = make_float4(0.f, 0.f, 0.f, 0.f);
    for (int m = 0; m < cnt; m++) {
        const float4 h = *(const float4*)&hidden[((size_t)b * LSEQ + s_match[m]) * DDIM + c];
        acc.x += h.x; acc.y += h.y; acc.z += h.z; acc.w += h.w;
    }
    float inv = 1.0f / (float)cnt;
    acc.x *= inv; acc.y *= inv; acc.z *= inv; acc.w *= inv;
    *(float4*)&g_pooled[(size_t)blk * DDIM + c] = acc;
}

// ---------------- kernel: fp32 -> fp16 convert ----------------
// grid 1024 x 256 = 262144 threads. A: 1048576 32B-units (4/thread). B: first 131072 threads.
__global__ __launch_bounds__(256) void convert_kernel(const float4* __restrict__ srcA,
                                                      uint4* __restrict__ dA,
                                                      const float4* __restrict__ srcB,
                                                      uint4* __restrict__ dB)
{
    const int T = 262144;
    int t = blockIdx.x * 256 + threadIdx.x;
#pragma unroll
    for (int it = 0; it < 4; it++) {
        int u = t + it * T;
        float4 v0 = srcA[2 * u];
        float4 v1 = srcA[2 * u + 1];
        uint4 o;
        o.x = pack2h(v0.x, v0.y);
        o.y = pack2h(v0.z, v0.w);
        o.z = pack2h(v1.x, v1.y);
        o.w = pack2h(v1.z, v1.w);
        dA[u] = o;
    }
    if (t < 131072) {
        float4 v0 = srcB[2 * t];
        float4 v1 = srcB[2 * t + 1];
        uint4 o;
        o.x = pack2h(v0.x, v0.y);
        o.y = pack2h(v0.z, v0.w);
        o.z = pack2h(v1.x, v1.y);
        o.w = pack2h(v1.z, v1.w);
        dB[t] = o;
    }
}

// ---------------- kernel 3: fp16 HMMA GEMM  C = X@W1^T + b1 + b2 ----------------
static constexpr int TBM = 128, TBN = 256, TBK = 64;
static constexpr int N_CHUNKS = KDIM / TBK;                      // 16
static constexpr int ST_AH = 0, ST_BH = 16384;
static constexpr int STAGE_BYTES = 49152;
static constexpr int N_STAGES = 4;
static constexpr int SMEM_DYN = 1024 + N_STAGES * STAGE_BYTES;

__global__ __launch_bounds__(256, 1)
void gemm_mma_kernel(const float* __restrict__ b1,
                     const float* __restrict__ b2,
                     float* __restrict__ C)
{
    extern __shared__ char smem[];
    uint32_t sbase = (smem_u32(smem) + 1023u) & ~1023u;

    int tid  = threadIdx.x;
    int wid  = tid >> 5;
    int lane = tid & 31;
    int row0 = blockIdx.y * TBM;
    int col0 = blockIdx.x * TBN;

    int wm = wid >> 2;
    int wn = wid & 3;
    int mbase = wm * 64;
    int nbase = wn * 64;

    int arow_l = (lane & 15);
    int aklane = (lane >> 4) * 16;
    uint32_t aoffs[4], axors[4];
#pragma unroll
    for (int i = 0; i < 4; i++) {
        int r = mbase + 16 * i + arow_l;
        aoffs[i] = (uint32_t)(r * 128);
        axors[i] = (uint32_t)((r & 7) << 4);
    }
    int btile_l = lane >> 4;
    int brow_l  = lane & 7;
    int bkhalf16 = ((lane >> 3) & 1) * 16;
    uint32_t bxor = (uint32_t)(brow_l << 4);
    uint32_t boffs4[4];
#pragma unroll
    for (int jp = 0; jp < 4; jp++)
        boffs4[jp] = (uint32_t)((nbase + 8 * (2 * jp + btile_l) + brow_l) * 128);

    float acc[4][8][4];
#pragma unroll
    for (int i = 0; i < 4; i++)
#pragma unroll
        for (int j = 0; j < 8; j++)
#pragma unroll
            for (int t = 0; t < 4; t++) acc[i][j][t] = 0.f;

    auto load_chunk = [&](int c) {
        uint32_t sb = sbase + (uint32_t)(c & (N_STAGES - 1)) * STAGE_BYTES;
        int k0 = c * TBK;
        for (int i = tid; i < 1024; i += 256) {
            int r = i >> 3, c16 = i & 7;
            uint32_t off = (uint32_t)(r * 128 + c16 * 16) ^ (uint32_t)((r & 7) << 4);
            cp16(sb + ST_AH + off, &g_Ah[(size_t)(row0 + r) * KDIM + k0 + c16 * 8]);
        }
        for (int i = tid; i < 2048; i += 256) {
            int r = i >> 3, c16 = i & 7;
            uint32_t off = (uint32_t)(r * 128 + c16 * 16) ^ (uint32_t)((r & 7) << 4);
            cp16(sb + ST_BH + off, &g_Bh[(size_t)(col0 + r) * KDIM + k0 + c16 * 8]);
        }
        CP_COMMIT();
    };

    uint32_t af[2][4][4], bf[2][8][2];
    auto load_frags = [&](uint32_t sb, int ks, int buf) {
        uint32_t kb = (uint32_t)(ks * 32);
        uint32_t akcol = kb + (uint32_t)aklane;
        uint32_t bkcol = kb + (uint32_t)bkhalf16;
#pragma unroll
        for (int i = 0; i < 4; i++)
            ldsm_x4(af[buf][i], sb + ST_AH + aoffs[i] + (akcol ^ axors[i]));
#pragma unroll
        for (int jp = 0; jp < 4; jp++)
            ldsm_x4(&bf[buf][2 * jp][0], sb + ST_BH + boffs4[jp] + (bkcol ^ bxor));
    };

    load_chunk(0);
    load_chunk(1);
    load_chunk(2);

#pragma unroll 1
    for (int c = 0; c < N_CHUNKS; c++) {
        if (c <= N_CHUNKS - 3)      CP_WAIT(2);
        else if (c == N_CHUNKS - 2) CP_WAIT(1);
        else                        CP_WAIT(0);
        __syncthreads();

        if (c + 3 < N_CHUNKS) load_chunk(c + 3);

        uint32_t sb = sbase + (uint32_t)(c & (N_STAGES - 1)) * STAGE_BYTES;
        load_frags(sb, 0, 0);
#pragma unroll
        for (int ks = 0; ks < 4; ks++) {
            int cur = ks & 1, nxt = cur ^ 1;
            if (ks < 3) load_frags(sb, ks + 1, nxt);
#pragma unroll
            for (int i = 0; i < 4; i++)
#pragma unroll
                for (int j = 0; j < 8; j++)
                    mma_f16(acc[i][j], af[cur][i], bf[cur][j]);
        }
    }

    int quad = lane >> 2;
    int tq   = lane & 3;
#pragma unroll
    for (int j = 0; j < 8; j++) {
        int col = col0 + nbase + 8 * j + tq * 2;
        float2 s1 = *(const float2*)&b1[col];
        float2 s2 = *(const float2*)&b2[col];
        float bx = s1.x + s2.x, by = s1.y + s2.y;
#pragma unroll
        for (int i = 0; i < 4; i++) {
            int r0 = row0 + mbase + 16 * i + quad;
            *(float2*)&C[(size_t)r0 * NCOLS + col] =
                make_float2(acc[i][j][0] + bx, acc[i][j][1] + by);
            *(float2*)&C[(size_t)(r0 + 8) * NCOLS + col] =
                make_float2(acc[i][j][2] + bx, acc[i][j][3] + by);
        }
    }
}

// ---------------- kernel 4: sparse fixup, 8-row-tiled  out[row] += pooled[row]@W2^T ----------------
// grid (32, 8). Tile t covers worklist slots [8t, 8t+8); block x strides tiles,
// block y owns a 128-column slice. W2 slice read once per 8 rows (8x less L2 traffic).
__global__ __launch_bounds__(256) void fixup_kernel(const float* __restrict__ W2,
                                                    float* __restrict__ C)
{
    __shared__ float s_x[8][1028];     // pad 4 floats: avoids 8-way bank conflict
    __shared__ int s_rows[8];
    int cnt = g_wl_count;
    int ntiles = (cnt + 7) >> 3;
    int tid  = threadIdx.x;
    int warp = tid >> 5;
    int lane = tid & 31;
    int colbase = blockIdx.y * 128;

    for (int t = blockIdx.x; t < ntiles; t += 32) {
        int base = t * 8;
        int nr = min(8, cnt - base);
        for (int i = tid; i < 8 * 1024; i += 256) {
            int r = i >> 10, d = i & 1023;
            s_x[r][d] = (r < nr) ? g_pooled[(size_t)g_wl[base + r] * DDIM + d] : 0.f;
        }
        if (tid < 8) s_rows[tid] = (tid < nr) ? g_wl[base + tid] : -1;
        __syncthreads();

        for (int jj = 0; jj < 16; jj++) {
            int j = colbase + warp * 16 + jj;
            const float* wrow = &W2[(size_t)j * KDIM + lane];
            float s[8];
#pragma unroll
            for (int r = 0; r < 8; r++) s[r] = 0.f;
#pragma unroll
            for (int d = 0; d < 32; d++) {
                float w = wrow[d * 32];
#pragma unroll
                for (int r = 0; r < 8; r++)
                    s[r] += s_x[r][lane + d * 32] * w;
            }
#pragma unroll
            for (int r = 0; r < 8; r++) {
                float v = s[r];
#pragma unroll
                for (int off = 16; off > 0; off >>= 1)
                    v += __shfl_down_sync(0xFFFFFFFFu, v, off);
                if (lane == 0 && s_rows[r] >= 0)
                    C[(size_t)s_rows[r] * NCOLS + j] += v;
            }
        }
        __syncthreads();
    }
}

// ---------------- launch ----------------
extern "C" void kernel_launch(void* const* d_in, const int* in_sizes, int n_in,
                              void* d_out, int out_size)
{
    const float* hidden = (const float*)d_in[0];
    const void*  ids    = d_in[1];
    const float* W1     = (const float*)d_in[2];
    const float* b1     = (const float*)d_in[3];
    const float* W2     = (const float*)d_in[4];
    const float* b2     = (const float*)d_in[5];
    const int*   n_ptr  = (const int*)d_in[6];
    float*       out    = (float*)d_out;

    static bool attr_done = false;
    if (!attr_done) {
        cudaFuncSetAttribute(gemm_mma_kernel,
                             cudaFuncAttributeMaxDynamicSharedMemorySize, SMEM_DYN);
        attr_done = true;
    }

    void *pAh, *pBh;
    cudaGetSymbolAddress(&pAh, g_Ah);
    cudaGetSymbolAddress(&pBh, g_Bh);

    convert_kernel<<<1024, 256>>>((const float4*)hidden, (uint4*)pAh,
                                  (const float4*)W1, (uint4*)pBh);
    detect_kernel<<<1024, 256>>>((const unsigned int*)ids);
    prep_codes_kernel<<<(MROWS + 255) / 256, 256>>>(ids, n_ptr);
    dim3 ggrid(NCOLS / TBN, MROWS / TBM);   // (4, 64)
    gemm_mma_kernel<<<ggrid, 256, SMEM_DYN>>>(b1, b2, out);   // launch #4 for ncu
    pool_kernel<<<MROWS, 256>>>(hidden);
    dim3 fgrid(32, 8);
    fixup_kernel<<<fgrid, 256>>>(W2, out);
}